// round 1
// baseline (speedup 1.0000x reference)
#include <cuda_runtime.h>
#include <cstdint>
#include <cstddef>

#define BATCH 1024
#define DIM   1024
#define HID   4096
#define TSTEPS 16
#define BD (BATCH*DIM)

// Scratch (device globals; no allocations allowed)
__device__ float g_H[(size_t)BATCH * HID];     // tanh hidden activations
__device__ float g_Ytmp[BD];                   // RK4 intermediate state
__device__ float g_Yacc[BD];                   // RK4 accumulator

// ---- packed f32x2 helpers (Blackwell FFMA2 path) ----
__device__ __forceinline__ unsigned long long pack2(float x) {
    unsigned long long r;
    unsigned int xi = __float_as_uint(x);
    asm("mov.b64 %0, {%1, %1};" : "=l"(r) : "r"(xi));
    return r;
}
__device__ __forceinline__ void fma2(unsigned long long& c, unsigned long long a,
                                     unsigned long long b) {
    asm("fma.rn.f32x2 %0, %1, %2, %0;" : "+l"(c) : "l"(a), "l"(b));
}

// Fused GEMM: C[M,N] = A[M,K] @ B[K,N] (+ epilogue)
// EPI 0: C = tanh(acc + bias)                                  (layer 1)
// EPI 1: k=acc+bias; Yout = Yin + h/2*k; Yacc = Yin + h/6*k    (stage k1)
// EPI 2: k=acc+bias; Yout = Yin + h/2*k; Yacc += h/3*k         (stage k2)
// EPI 3: k=acc+bias; Yout = Yin + h  *k; Yacc += h/3*k         (stage k3)
// EPI 4: k=acc+bias; Yout = Yacc + h/6*k                       (stage k4 -> y_next)
template <int BM, int BN, int BK, int TM, int TN, int EPI>
__global__ void __launch_bounds__((BM / TM) * (BN / TN)) gemm_fused(
    const float* __restrict__ A, const float* __restrict__ B,
    const float* __restrict__ bias, float* __restrict__ C, int M, int N, int K,
    const float* __restrict__ Yin, float* __restrict__ Yacc,
    float* __restrict__ Yout, const float* __restrict__ tspan, int step) {
    constexpr int NT = (BM / TM) * (BN / TN);
    constexpr int TX = BN / TN;
    constexpr int A_LD = (BM * BK / 4) / NT;  // float4 loads per thread
    constexpr int B_LD = (BK * BN / 4) / NT;

    __shared__ float As[BK][BM + 4];
    __shared__ float Bs[BK][BN];

    const int tid = threadIdx.x;
    const int tx = tid % TX;
    const int ty = tid / TX;
    const int rowBase = blockIdx.y * BM;
    const int colBase = blockIdx.x * BN;

    unsigned long long acc[TM][TN / 2];
#pragma unroll
    for (int i = 0; i < TM; i++)
#pragma unroll
        for (int j = 0; j < TN / 2; j++) acc[i][j] = 0ULL;

    float4 ar[A_LD], br[B_LD];

    // prefetch first tiles to registers
#pragma unroll
    for (int u = 0; u < A_LD; u++) {
        int i = tid + u * NT;
        int r = i / (BK / 4);
        int c4 = (i % (BK / 4)) * 4;
        ar[u] = *(const float4*)(A + (size_t)(rowBase + r) * K + 0 + c4);
    }
#pragma unroll
    for (int u = 0; u < B_LD; u++) {
        int i = tid + u * NT;
        int r = i / (BN / 4);
        int c4 = (i % (BN / 4)) * 4;
        br[u] = *(const float4*)(B + (size_t)(0 + r) * N + colBase + c4);
    }

    for (int kt = 0; kt < K; kt += BK) {
        __syncthreads();  // smem safe to overwrite
        // store register-staged tiles to shared (A transposed)
#pragma unroll
        for (int u = 0; u < A_LD; u++) {
            int i = tid + u * NT;
            int r = i / (BK / 4);
            int c4 = (i % (BK / 4)) * 4;
            As[c4 + 0][r] = ar[u].x;
            As[c4 + 1][r] = ar[u].y;
            As[c4 + 2][r] = ar[u].z;
            As[c4 + 3][r] = ar[u].w;
        }
#pragma unroll
        for (int u = 0; u < B_LD; u++) {
            int i = tid + u * NT;
            int r = i / (BN / 4);
            int c4 = (i % (BN / 4)) * 4;
            *(float4*)(&Bs[r][c4]) = br[u];
        }
        __syncthreads();

        // prefetch next tiles (overlaps with compute below)
        const int ktn = kt + BK;
        if (ktn < K) {
#pragma unroll
            for (int u = 0; u < A_LD; u++) {
                int i = tid + u * NT;
                int r = i / (BK / 4);
                int c4 = (i % (BK / 4)) * 4;
                ar[u] = *(const float4*)(A + (size_t)(rowBase + r) * K + ktn + c4);
            }
#pragma unroll
            for (int u = 0; u < B_LD; u++) {
                int i = tid + u * NT;
                int r = i / (BN / 4);
                int c4 = (i % (BN / 4)) * 4;
                br[u] = *(const float4*)(B + (size_t)(ktn + r) * N + colBase + c4);
            }
        }

#pragma unroll
        for (int kk = 0; kk < BK; kk++) {
            float av[TM];
#pragma unroll
            for (int i = 0; i < TM; i++) av[i] = As[kk][ty * TM + i];
            unsigned long long bv[TN / 2];
#pragma unroll
            for (int j = 0; j < TN / 2; j++)
                bv[j] = *(const unsigned long long*)(&Bs[kk][tx * TN + 2 * j]);
#pragma unroll
            for (int i = 0; i < TM; i++) {
                unsigned long long ap = pack2(av[i]);
#pragma unroll
                for (int j = 0; j < TN / 2; j++) fma2(acc[i][j], ap, bv[j]);
            }
        }
    }

    // ---- epilogue ----
    float hstep = 0.0f;
    if (EPI >= 1) hstep = tspan[step + 1] - tspan[step];

#pragma unroll
    for (int i = 0; i < TM; i++) {
        const int row = rowBase + ty * TM + i;
#pragma unroll
        for (int j = 0; j < TN / 2; j++) {
            const float lo = __uint_as_float((unsigned int)(acc[i][j] & 0xffffffffull));
            const float hi = __uint_as_float((unsigned int)(acc[i][j] >> 32));
#pragma unroll
            for (int e = 0; e < 2; e++) {
                const int col = colBase + tx * TN + 2 * j + e;
                const float val = (e ? hi : lo) + bias[col];
                const size_t gidx = (size_t)row * N + col;
                if (EPI == 0) {
                    C[gidx] = tanhf(val);
                } else if (EPI == 1) {
                    const float y0 = Yin[gidx];
                    Yout[gidx] = y0 + 0.5f * hstep * val;
                    Yacc[gidx] = y0 + (hstep * (1.0f / 6.0f)) * val;
                } else if (EPI == 2) {
                    const float y0 = Yin[gidx];
                    Yout[gidx] = y0 + 0.5f * hstep * val;
                    Yacc[gidx] += (hstep * (1.0f / 3.0f)) * val;
                } else if (EPI == 3) {
                    const float y0 = Yin[gidx];
                    Yout[gidx] = y0 + hstep * val;
                    Yacc[gidx] += (hstep * (1.0f / 3.0f)) * val;
                } else {  // EPI == 4
                    Yout[gidx] = Yacc[gidx] + (hstep * (1.0f / 6.0f)) * val;
                }
            }
        }
    }
}

extern "C" void kernel_launch(void* const* d_in, const int* in_sizes, int n_in,
                              void* d_out, int out_size) {
    const float* y_init = (const float*)d_in[0];
    const float* tspan = (const float*)d_in[1];
    const float* W1 = (const float*)d_in[2];
    const float* b1 = (const float*)d_in[3];
    const float* W2 = (const float*)d_in[4];
    const float* b2 = (const float*)d_in[5];
    float* out = (float*)d_out;

    float *H, *Ytmp, *Yacc;
    cudaGetSymbolAddress((void**)&H, g_H);
    cudaGetSymbolAddress((void**)&Ytmp, g_Ytmp);
    cudaGetSymbolAddress((void**)&Yacc, g_Yacc);

    // out = [ t_span (16) | traj (16 x 1024 x 1024) ], traj[0] = y_init
    cudaMemcpyAsync(out, tspan, TSTEPS * sizeof(float),
                    cudaMemcpyDeviceToDevice, 0);
    float* traj = out + TSTEPS;
    cudaMemcpyAsync(traj, y_init, (size_t)BD * sizeof(float),
                    cudaMemcpyDeviceToDevice, 0);

    const dim3 grid1(HID / 128, BATCH / 128);  // (32, 8) = 256 blocks
    const dim3 blk1(256);
    const dim3 grid2(DIM / 64, BATCH / 128);   // (16, 8) = 128 blocks
    const dim3 blk2(128);

    for (int s = 0; s < TSTEPS - 1; ++s) {
        const float* y = traj + (size_t)s * BD;
        float* ynext = traj + (size_t)(s + 1) * BD;

        // stage 1: k1 from y
        gemm_fused<128, 128, 16, 8, 8, 0><<<grid1, blk1>>>(
            y, W1, b1, H, BATCH, HID, DIM, nullptr, nullptr, nullptr, tspan, s);
        gemm_fused<128, 64, 16, 8, 8, 1><<<grid2, blk2>>>(
            H, W2, b2, nullptr, BATCH, DIM, HID, y, Yacc, Ytmp, tspan, s);
        // stage 2: k2 from y + h/2*k1
        gemm_fused<128, 128, 16, 8, 8, 0><<<grid1, blk1>>>(
            Ytmp, W1, b1, H, BATCH, HID, DIM, nullptr, nullptr, nullptr, tspan, s);
        gemm_fused<128, 64, 16, 8, 8, 2><<<grid2, blk2>>>(
            H, W2, b2, nullptr, BATCH, DIM, HID, y, Yacc, Ytmp, tspan, s);
        // stage 3: k3 from y + h/2*k2
        gemm_fused<128, 128, 16, 8, 8, 0><<<grid1, blk1>>>(
            Ytmp, W1, b1, H, BATCH, HID, DIM, nullptr, nullptr, nullptr, tspan, s);
        gemm_fused<128, 64, 16, 8, 8, 3><<<grid2, blk2>>>(
            H, W2, b2, nullptr, BATCH, DIM, HID, y, Yacc, Ytmp, tspan, s);
        // stage 4: k4 from y + h*k3 ; y_next = yacc + h/6*k4
        gemm_fused<128, 128, 16, 8, 8, 0><<<grid1, blk1>>>(
            Ytmp, W1, b1, H, BATCH, HID, DIM, nullptr, nullptr, nullptr, tspan, s);
        gemm_fused<128, 64, 16, 8, 8, 4><<<grid2, blk2>>>(
            H, W2, b2, nullptr, BATCH, DIM, HID, nullptr, Yacc, ynext, tspan, s);
    }
}

// round 2
// speedup vs baseline: 1.0002x; 1.0002x over previous
#include <cuda_runtime.h>
#include <cstdint>
#include <cstddef>

#define BATCH 1024
#define DIM   1024
#define HID   4096
#define TSTEPS 16
#define BD (BATCH*DIM)

// Scratch (device globals; no allocations allowed)
__device__ float g_H[(size_t)BATCH * HID];     // tanh hidden activations
__device__ float g_Ytmp[BD];                   // RK4 intermediate state
__device__ float g_Yacc[BD];                   // RK4 accumulator

// ---- packed f32x2 helpers (Blackwell FFMA2 path) ----
__device__ __forceinline__ unsigned long long pack2(float x) {
    unsigned long long r;
    unsigned int xi = __float_as_uint(x);
    asm("mov.b64 %0, {%1, %1};" : "=l"(r) : "r"(xi));
    return r;
}
__device__ __forceinline__ void fma2(unsigned long long& c, unsigned long long a,
                                     unsigned long long b) {
    asm("fma.rn.f32x2 %0, %1, %2, %0;" : "+l"(c) : "l"(a), "l"(b));
}

// Fused GEMM: C[M,N] = A[M,K] @ B[K,N] (+ epilogue)
// EPI 0: C = tanh(acc + bias)                                  (layer 1)
// EPI 1: k=acc+bias; Yout = Yin + h/2*k; Yacc = Yin + h/6*k    (stage k1)
// EPI 2: k=acc+bias; Yout = Yin + h/2*k; Yacc += h/3*k         (stage k2)
// EPI 3: k=acc+bias; Yout = Yin + h  *k; Yacc += h/3*k         (stage k3)
// EPI 4: k=acc+bias; Yout = Yacc + h/6*k                       (stage k4 -> y_next)
template <int BM, int BN, int BK, int TM, int TN, int EPI>
__global__ void __launch_bounds__((BM / TM) * (BN / TN)) gemm_fused(
    const float* __restrict__ A, const float* __restrict__ B,
    const float* __restrict__ bias, float* __restrict__ C, int M, int N, int K,
    const float* __restrict__ Yin, float* __restrict__ Yacc,
    float* __restrict__ Yout, const float* __restrict__ tspan, int step) {
    constexpr int NT = (BM / TM) * (BN / TN);
    constexpr int TX = BN / TN;
    constexpr int A_LD = (BM * BK / 4) / NT;  // float4 loads per thread
    constexpr int B_LD = (BK * BN / 4) / NT;

    __shared__ float As[BK][BM + 4];
    __shared__ float Bs[BK][BN];

    const int tid = threadIdx.x;
    const int tx = tid % TX;
    const int ty = tid / TX;
    const int rowBase = blockIdx.y * BM;
    const int colBase = blockIdx.x * BN;

    unsigned long long acc[TM][TN / 2];
#pragma unroll
    for (int i = 0; i < TM; i++)
#pragma unroll
        for (int j = 0; j < TN / 2; j++) acc[i][j] = 0ULL;

    float4 ar[A_LD], br[B_LD];

    // prefetch first tiles to registers
#pragma unroll
    for (int u = 0; u < A_LD; u++) {
        int i = tid + u * NT;
        int r = i / (BK / 4);
        int c4 = (i % (BK / 4)) * 4;
        ar[u] = *(const float4*)(A + (size_t)(rowBase + r) * K + 0 + c4);
    }
#pragma unroll
    for (int u = 0; u < B_LD; u++) {
        int i = tid + u * NT;
        int r = i / (BN / 4);
        int c4 = (i % (BN / 4)) * 4;
        br[u] = *(const float4*)(B + (size_t)(0 + r) * N + colBase + c4);
    }

    for (int kt = 0; kt < K; kt += BK) {
        __syncthreads();  // smem safe to overwrite
        // store register-staged tiles to shared (A transposed)
#pragma unroll
        for (int u = 0; u < A_LD; u++) {
            int i = tid + u * NT;
            int r = i / (BK / 4);
            int c4 = (i % (BK / 4)) * 4;
            As[c4 + 0][r] = ar[u].x;
            As[c4 + 1][r] = ar[u].y;
            As[c4 + 2][r] = ar[u].z;
            As[c4 + 3][r] = ar[u].w;
        }
#pragma unroll
        for (int u = 0; u < B_LD; u++) {
            int i = tid + u * NT;
            int r = i / (BN / 4);
            int c4 = (i % (BN / 4)) * 4;
            *(float4*)(&Bs[r][c4]) = br[u];
        }
        __syncthreads();

        // prefetch next tiles (overlaps with compute below)
        const int ktn = kt + BK;
        if (ktn < K) {
#pragma unroll
            for (int u = 0; u < A_LD; u++) {
                int i = tid + u * NT;
                int r = i / (BK / 4);
                int c4 = (i % (BK / 4)) * 4;
                ar[u] = *(const float4*)(A + (size_t)(rowBase + r) * K + ktn + c4);
            }
#pragma unroll
            for (int u = 0; u < B_LD; u++) {
                int i = tid + u * NT;
                int r = i / (BN / 4);
                int c4 = (i % (BN / 4)) * 4;
                br[u] = *(const float4*)(B + (size_t)(ktn + r) * N + colBase + c4);
            }
        }

#pragma unroll
        for (int kk = 0; kk < BK; kk++) {
            float av[TM];
#pragma unroll
            for (int i = 0; i < TM; i++) av[i] = As[kk][ty * TM + i];
            unsigned long long bv[TN / 2];
#pragma unroll
            for (int j = 0; j < TN / 2; j++)
                bv[j] = *(const unsigned long long*)(&Bs[kk][tx * TN + 2 * j]);
#pragma unroll
            for (int i = 0; i < TM; i++) {
                unsigned long long ap = pack2(av[i]);
#pragma unroll
                for (int j = 0; j < TN / 2; j++) fma2(acc[i][j], ap, bv[j]);
            }
        }
    }

    // ---- epilogue ----
    float hstep = 0.0f;
    if (EPI >= 1) hstep = tspan[step + 1] - tspan[step];

#pragma unroll
    for (int i = 0; i < TM; i++) {
        const int row = rowBase + ty * TM + i;
#pragma unroll
        for (int j = 0; j < TN / 2; j++) {
            const float lo = __uint_as_float((unsigned int)(acc[i][j] & 0xffffffffull));
            const float hi = __uint_as_float((unsigned int)(acc[i][j] >> 32));
#pragma unroll
            for (int e = 0; e < 2; e++) {
                const int col = colBase + tx * TN + 2 * j + e;
                const float val = (e ? hi : lo) + bias[col];
                const size_t gidx = (size_t)row * N + col;
                if (EPI == 0) {
                    C[gidx] = tanhf(val);
                } else if (EPI == 1) {
                    const float y0 = Yin[gidx];
                    Yout[gidx] = y0 + 0.5f * hstep * val;
                    Yacc[gidx] = y0 + (hstep * (1.0f / 6.0f)) * val;
                } else if (EPI == 2) {
                    const float y0 = Yin[gidx];
                    Yout[gidx] = y0 + 0.5f * hstep * val;
                    Yacc[gidx] += (hstep * (1.0f / 3.0f)) * val;
                } else if (EPI == 3) {
                    const float y0 = Yin[gidx];
                    Yout[gidx] = y0 + hstep * val;
                    Yacc[gidx] += (hstep * (1.0f / 3.0f)) * val;
                } else {  // EPI == 4
                    Yout[gidx] = Yacc[gidx] + (hstep * (1.0f / 6.0f)) * val;
                }
            }
        }
    }
}

extern "C" void kernel_launch(void* const* d_in, const int* in_sizes, int n_in,
                              void* d_out, int out_size) {
    const float* y_init = (const float*)d_in[0];
    const float* tspan = (const float*)d_in[1];
    const float* W1 = (const float*)d_in[2];
    const float* b1 = (const float*)d_in[3];
    const float* W2 = (const float*)d_in[4];
    const float* b2 = (const float*)d_in[5];
    float* out = (float*)d_out;

    float *H, *Ytmp, *Yacc;
    cudaGetSymbolAddress((void**)&H, g_H);
    cudaGetSymbolAddress((void**)&Ytmp, g_Ytmp);
    cudaGetSymbolAddress((void**)&Yacc, g_Yacc);

    // out = [ t_span (16) | traj (16 x 1024 x 1024) ], traj[0] = y_init
    cudaMemcpyAsync(out, tspan, TSTEPS * sizeof(float),
                    cudaMemcpyDeviceToDevice, 0);
    float* traj = out + TSTEPS;
    cudaMemcpyAsync(traj, y_init, (size_t)BD * sizeof(float),
                    cudaMemcpyDeviceToDevice, 0);

    const dim3 grid1(HID / 128, BATCH / 128);  // (32, 8) = 256 blocks
    const dim3 blk1(256);
    const dim3 grid2(DIM / 64, BATCH / 128);   // (16, 8) = 128 blocks
    const dim3 blk2(128);

    for (int s = 0; s < TSTEPS - 1; ++s) {
        const float* y = traj + (size_t)s * BD;
        float* ynext = traj + (size_t)(s + 1) * BD;

        // stage 1: k1 from y
        gemm_fused<128, 128, 16, 8, 8, 0><<<grid1, blk1>>>(
            y, W1, b1, H, BATCH, HID, DIM, nullptr, nullptr, nullptr, tspan, s);
        gemm_fused<128, 64, 16, 8, 8, 1><<<grid2, blk2>>>(
            H, W2, b2, nullptr, BATCH, DIM, HID, y, Yacc, Ytmp, tspan, s);
        // stage 2: k2 from y + h/2*k1
        gemm_fused<128, 128, 16, 8, 8, 0><<<grid1, blk1>>>(
            Ytmp, W1, b1, H, BATCH, HID, DIM, nullptr, nullptr, nullptr, tspan, s);
        gemm_fused<128, 64, 16, 8, 8, 2><<<grid2, blk2>>>(
            H, W2, b2, nullptr, BATCH, DIM, HID, y, Yacc, Ytmp, tspan, s);
        // stage 3: k3 from y + h/2*k2
        gemm_fused<128, 128, 16, 8, 8, 0><<<grid1, blk1>>>(
            Ytmp, W1, b1, H, BATCH, HID, DIM, nullptr, nullptr, nullptr, tspan, s);
        gemm_fused<128, 64, 16, 8, 8, 3><<<grid2, blk2>>>(
            H, W2, b2, nullptr, BATCH, DIM, HID, y, Yacc, Ytmp, tspan, s);
        // stage 4: k4 from y + h*k3 ; y_next = yacc + h/6*k4
        gemm_fused<128, 128, 16, 8, 8, 0><<<grid1, blk1>>>(
            Ytmp, W1, b1, H, BATCH, HID, DIM, nullptr, nullptr, nullptr, tspan, s);
        gemm_fused<128, 64, 16, 8, 8, 4><<<grid2, blk2>>>(
            H, W2, b2, nullptr, BATCH, DIM, HID, nullptr, Yacc, ynext, tspan, s);
    }
}

// round 4
// speedup vs baseline: 3.6010x; 3.6003x over previous
#include <cuda_runtime.h>
#include <cuda_bf16.h>
#include <cstdint>
#include <cstddef>

#define BATCH 1024
#define DIM   1024
#define HID   4096
#define TSTEPS 16
#define BD (BATCH*DIM)

__device__ __nv_bfloat16 g_W1h[(size_t)HID * DIM];
__device__ __nv_bfloat16 g_W1l[(size_t)HID * DIM];
__device__ __nv_bfloat16 g_W2h[(size_t)DIM * HID];
__device__ __nv_bfloat16 g_W2l[(size_t)DIM * HID];
__device__ __nv_bfloat16 g_Hh[(size_t)BATCH * HID];
__device__ __nv_bfloat16 g_Hl[(size_t)BATCH * HID];
__device__ __nv_bfloat16 g_Yh[BD];
__device__ __nv_bfloat16 g_Yl[BD];
__device__ float         g_Yacc[BD];

__device__ __forceinline__ uint32_t smem_u32(const void* p) {
    uint32_t a;
    asm("{ .reg .u64 t; cvta.to.shared.u64 t, %1; cvt.u32.u64 %0, t; }" : "=r"(a) : "l"(p));
    return a;
}
__device__ __forceinline__ void cpa16(uint32_t s, const void* g) {
    asm volatile("cp.async.cg.shared.global [%0], [%1], 16;"
                 :: "r"(s), "l"(__cvta_generic_to_global(g)));
}
#define CP_COMMIT() asm volatile("cp.async.commit_group;" ::: "memory")
#define CP_WAIT0()  asm volatile("cp.async.wait_group 0;" ::: "memory")

__device__ __forceinline__ void ldsm4(uint32_t* r, uint32_t addr) {
    asm volatile("ldmatrix.sync.aligned.m8n8.x4.shared.b16 {%0,%1,%2,%3}, [%4];"
                 : "=r"(r[0]), "=r"(r[1]), "=r"(r[2]), "=r"(r[3]) : "r"(addr));
}
__device__ __forceinline__ void mma_bf16(float* d, const uint32_t* a, const uint32_t* b) {
    asm volatile(
        "mma.sync.aligned.m16n8k16.row.col.f32.bf16.bf16.f32 "
        "{%0,%1,%2,%3}, {%4,%5,%6,%7}, {%8,%9}, {%0,%1,%2,%3};"
        : "+f"(d[0]), "+f"(d[1]), "+f"(d[2]), "+f"(d[3])
        : "r"(a[0]), "r"(a[1]), "r"(a[2]), "r"(a[3]), "r"(b[0]), "r"(b[1]));
}

__device__ __forceinline__ uint32_t split_pack(float a0, float a1, uint32_t& lo) {
    __nv_bfloat16 h0 = __float2bfloat16(a0);
    __nv_bfloat16 h1 = __float2bfloat16(a1);
    __nv_bfloat16 l0 = __float2bfloat16(a0 - __bfloat162float(h0));
    __nv_bfloat16 l1 = __float2bfloat16(a1 - __bfloat162float(h1));
    lo = ((uint32_t)__bfloat16_as_ushort(l1) << 16) | __bfloat16_as_ushort(l0);
    return ((uint32_t)__bfloat16_as_ushort(h1) << 16) | __bfloat16_as_ushort(h0);
}

// C tile [128 x BN] of A[M,K] @ B[N,K]^T via mma.sync bf16, split hi/lo 3-term.
// A,B given as separate hi/lo planes, row-major [rows, K].
// EPI 0: O = tanh(acc+bias) -> Oh/Ol
// EPI 1: k=acc+bias; o=Yin+h/2*k; Yacc=Yin+h/6*k;  o->Oh/Ol
// EPI 2: k=acc+bias; o=Yin+h/2*k; Yacc+=h/3*k;     o->Oh/Ol
// EPI 3: k=acc+bias; o=Yin+h*k;   Yacc+=h/3*k;     o->Oh/Ol
// EPI 4: k=acc+bias; o=Yacc+h/6*k; o->Yout(f32) and Oh/Ol
template <int BN, int EPI>
__global__ void __launch_bounds__(256, 1)
hmma_gemm(const __nv_bfloat16* __restrict__ Ah, const __nv_bfloat16* __restrict__ Al,
          const __nv_bfloat16* __restrict__ Bh, const __nv_bfloat16* __restrict__ Bl,
          const float* __restrict__ bias, int K, int ldc,
          __nv_bfloat16* __restrict__ Oh, __nv_bfloat16* __restrict__ Ol,
          const float* __restrict__ Yin, float* __restrict__ Yacc,
          float* __restrict__ Yout, const float* __restrict__ tspan, int step) {
    constexpr int NT = BN / 16;          // n8 fragments per warp (warp covers BN/2 cols)
    constexpr int APLANE = 128 * 128;    // bytes: 128 rows x 128B (BK=64 bf16)
    constexpr int BPLANE = BN * 128;
    constexpr int STAGE = 2 * APLANE + 2 * BPLANE;
    extern __shared__ char smem[];
    const uint32_t sb0 = smem_u32(smem);

    const int tid = threadIdx.x;
    const int wid = tid >> 5, lane = tid & 31;
    const int wm = wid & 3, wn = wid >> 2;
    const int gid = lane >> 2, tig = lane & 3;
    const int rowBase = blockIdx.y * 128;
    const int colBase = blockIdx.x * BN;
    const int NC = K >> 6;

    auto load_stage = [&](int kc, int st) {
        const uint32_t sb = sb0 + st * STAGE;
        const size_t keB = (size_t)kc * 128;  // byte offset along K
#pragma unroll
        for (int c = tid; c < 128 * 8; c += 256) {
            const int row = c >> 3, kb = (c & 7) << 4;
            const uint32_t so = row * 128 + (kb ^ ((row & 7) << 4));
            const size_t g = (size_t)(rowBase + row) * (K * 2) + keB + kb;
            cpa16(sb + so, (const char*)Ah + g);
            cpa16(sb + APLANE + so, (const char*)Al + g);
        }
#pragma unroll
        for (int c = tid; c < BN * 8; c += 256) {
            const int row = c >> 3, kb = (c & 7) << 4;
            const uint32_t so = row * 128 + (kb ^ ((row & 7) << 4));
            const size_t g = (size_t)(colBase + row) * (K * 2) + keB + kb;
            cpa16(sb + 2 * APLANE + so, (const char*)Bh + g);
            cpa16(sb + 2 * APLANE + BPLANE + so, (const char*)Bl + g);
        }
    };

    float acc[2][NT][4];
#pragma unroll
    for (int i = 0; i < 2; ++i)
#pragma unroll
        for (int j = 0; j < NT; ++j)
#pragma unroll
            for (int e = 0; e < 4; ++e) acc[i][j][e] = 0.f;

    load_stage(0, 0);
    CP_COMMIT();

    for (int kc = 0; kc < NC; ++kc) {
        CP_WAIT0();
        __syncthreads();
        if (kc + 1 < NC) { load_stage(kc + 1, (kc + 1) & 1); CP_COMMIT(); }
        const uint32_t sb = sb0 + (kc & 1) * STAGE;
#pragma unroll
        for (int t = 0; t < 4; ++t) {  // four k16 slices per BK=64 chunk
            uint32_t af[2][2][4];      // [plane hi/lo][mi][4 regs]
#pragma unroll
            for (int mi = 0; mi < 2; ++mi) {
                const int arow = wm * 32 + mi * 16 + (lane & 15);
                const int kb = t * 32 + ((lane >> 4) << 4);
                const uint32_t so = arow * 128 + (kb ^ ((arow & 7) << 4));
                ldsm4(af[0][mi], sb + so);
                ldsm4(af[1][mi], sb + APLANE + so);
            }
            uint32_t bfh[NT * 2], bfl[NT * 2];
#pragma unroll
            for (int bi = 0; bi < NT / 2; ++bi) {
                const int brow = wn * (BN / 2) + bi * 16 + ((lane >> 4) << 3) + (lane & 7);
                const int kb = t * 32 + (((lane >> 3) & 1) << 4);
                const uint32_t so = brow * 128 + (kb ^ ((brow & 7) << 4));
                ldsm4(&bfh[bi * 4], sb + 2 * APLANE + so);
                ldsm4(&bfl[bi * 4], sb + 2 * APLANE + BPLANE + so);
            }
#pragma unroll
            for (int mi = 0; mi < 2; ++mi)
#pragma unroll
                for (int ni = 0; ni < NT; ++ni) {
                    mma_bf16(acc[mi][ni], af[0][mi], &bfh[ni * 2]);
                    mma_bf16(acc[mi][ni], af[0][mi], &bfl[ni * 2]);
                    mma_bf16(acc[mi][ni], af[1][mi], &bfh[ni * 2]);
                }
        }
    }

    float h = 0.f;
    if (EPI >= 1) h = tspan[step + 1] - tspan[step];

    auto emit = [&](int row, int col, float v0, float v1) {
        const float2 bb = *reinterpret_cast<const float2*>(bias + col);
        v0 += bb.x;
        v1 += bb.y;
        const size_t ix = (size_t)row * ldc + col;
        float o0, o1;
        if (EPI == 0) {
            o0 = tanhf(v0);
            o1 = tanhf(v1);
        } else if (EPI == 1) {
            const float2 yy = *reinterpret_cast<const float2*>(Yin + ix);
            o0 = fmaf(0.5f * h, v0, yy.x);
            o1 = fmaf(0.5f * h, v1, yy.y);
            float2 aa;
            aa.x = fmaf(h * (1.f / 6.f), v0, yy.x);
            aa.y = fmaf(h * (1.f / 6.f), v1, yy.y);
            *reinterpret_cast<float2*>(Yacc + ix) = aa;
        } else if (EPI == 2 || EPI == 3) {
            const float cy = (EPI == 2) ? 0.5f : 1.0f;
            const float2 yy = *reinterpret_cast<const float2*>(Yin + ix);
            float2 aa = *reinterpret_cast<float2*>(Yacc + ix);
            o0 = fmaf(cy * h, v0, yy.x);
            o1 = fmaf(cy * h, v1, yy.y);
            aa.x = fmaf(h * (1.f / 3.f), v0, aa.x);
            aa.y = fmaf(h * (1.f / 3.f), v1, aa.y);
            *reinterpret_cast<float2*>(Yacc + ix) = aa;
        } else {
            const float2 aa = *reinterpret_cast<const float2*>(Yacc + ix);
            o0 = fmaf(h * (1.f / 6.f), v0, aa.x);
            o1 = fmaf(h * (1.f / 6.f), v1, aa.y);
            float2 oo;
            oo.x = o0;
            oo.y = o1;
            *reinterpret_cast<float2*>(Yout + ix) = oo;
        }
        uint32_t lo;
        const uint32_t hi = split_pack(o0, o1, lo);
        *reinterpret_cast<uint32_t*>(Oh + ix) = hi;
        *reinterpret_cast<uint32_t*>(Ol + ix) = lo;
    };

#pragma unroll
    for (int mi = 0; mi < 2; ++mi) {
        const int row = rowBase + wm * 32 + mi * 16 + gid;
#pragma unroll
        for (int ni = 0; ni < NT; ++ni) {
            const int col = colBase + wn * (BN / 2) + ni * 8 + tig * 2;
            emit(row, col, acc[mi][ni][0], acc[mi][ni][1]);
            emit(row + 8, col, acc[mi][ni][2], acc[mi][ni][3]);
        }
    }
}

__global__ void ktrans_split(const float* __restrict__ in,
                             __nv_bfloat16* __restrict__ oh,
                             __nv_bfloat16* __restrict__ ol, int R, int C) {
    __shared__ float t[32][33];
    const int bx = blockIdx.x * 32;
    const int by = blockIdx.y * 32;
    for (int i = threadIdx.y; i < 32; i += 8)
        t[i][threadIdx.x] = in[(size_t)(by + i) * C + bx + threadIdx.x];
    __syncthreads();
    for (int i = threadIdx.y; i < 32; i += 8) {
        float v = t[threadIdx.x][i];
        size_t o = (size_t)(bx + i) * R + by + threadIdx.x;
        __nv_bfloat16 hb = __float2bfloat16(v);
        oh[o] = hb;
        ol[o] = __float2bfloat16(v - __bfloat162float(hb));
    }
}

__global__ void ksplit(const float* __restrict__ in, __nv_bfloat16* __restrict__ oh,
                       __nv_bfloat16* __restrict__ ol, int n) {
    int i = blockIdx.x * 256 + threadIdx.x;
    if (i < n) {
        float v = in[i];
        __nv_bfloat16 hb = __float2bfloat16(v);
        oh[i] = hb;
        ol[i] = __float2bfloat16(v - __bfloat162float(hb));
    }
}

extern "C" void kernel_launch(void* const* d_in, const int* in_sizes, int n_in,
                              void* d_out, int out_size) {
    const float* y_init = (const float*)d_in[0];
    const float* tspan = (const float*)d_in[1];
    const float* W1 = (const float*)d_in[2];
    const float* b1 = (const float*)d_in[3];
    const float* W2 = (const float*)d_in[4];
    const float* b2 = (const float*)d_in[5];
    float* out = (float*)d_out;

    __nv_bfloat16 *W1h, *W1l, *W2h, *W2l, *Hh, *Hl, *Yh, *Yl;
    float* Yacc;
    cudaGetSymbolAddress((void**)&W1h, g_W1h);
    cudaGetSymbolAddress((void**)&W1l, g_W1l);
    cudaGetSymbolAddress((void**)&W2h, g_W2h);
    cudaGetSymbolAddress((void**)&W2l, g_W2l);
    cudaGetSymbolAddress((void**)&Hh, g_Hh);
    cudaGetSymbolAddress((void**)&Hl, g_Hl);
    cudaGetSymbolAddress((void**)&Yh, g_Yh);
    cudaGetSymbolAddress((void**)&Yl, g_Yl);
    cudaGetSymbolAddress((void**)&Yacc, g_Yacc);

    // dynamic smem: 2 stages x (2 A planes + 2 B planes)
    const int SM1 = 2 * (2 * 128 * 128 + 2 * 128 * 128);  // 131072 (BN=128)
    const int SM2 = 2 * (2 * 128 * 128 + 2 * 64 * 128);   // 98304  (BN=64)
    cudaFuncSetAttribute(hmma_gemm<128, 0>, cudaFuncAttributeMaxDynamicSharedMemorySize, SM1);
    cudaFuncSetAttribute(hmma_gemm<64, 1>, cudaFuncAttributeMaxDynamicSharedMemorySize, SM2);
    cudaFuncSetAttribute(hmma_gemm<64, 2>, cudaFuncAttributeMaxDynamicSharedMemorySize, SM2);
    cudaFuncSetAttribute(hmma_gemm<64, 3>, cudaFuncAttributeMaxDynamicSharedMemorySize, SM2);
    cudaFuncSetAttribute(hmma_gemm<64, 4>, cudaFuncAttributeMaxDynamicSharedMemorySize, SM2);

    // out = [ t_span (16) | traj (16 x 1024 x 1024) ], traj[0] = y_init
    cudaMemcpyAsync(out, tspan, TSTEPS * sizeof(float), cudaMemcpyDeviceToDevice, 0);
    float* traj = out + TSTEPS;
    cudaMemcpyAsync(traj, y_init, (size_t)BD * sizeof(float), cudaMemcpyDeviceToDevice, 0);

    ktrans_split<<<dim3(HID / 32, DIM / 32), dim3(32, 8)>>>(W1, W1h, W1l, DIM, HID);
    ktrans_split<<<dim3(DIM / 32, HID / 32), dim3(32, 8)>>>(W2, W2h, W2l, HID, DIM);
    ksplit<<<BD / 256, 256>>>(y_init, Yh, Yl, BD);

    const dim3 g1(HID / 128, BATCH / 128);  // (32, 8) = 256 CTAs
    const dim3 g2(DIM / 64, BATCH / 128);   // (16, 8) = 128 CTAs

    for (int s = 0; s < TSTEPS - 1; ++s) {
        const float* y = traj + (size_t)s * BD;
        float* ynext = traj + (size_t)(s + 1) * BD;

        hmma_gemm<128, 0><<<g1, 256, SM1>>>(Yh, Yl, W1h, W1l, b1, DIM, HID,
                                            Hh, Hl, nullptr, nullptr, nullptr, tspan, s);
        hmma_gemm<64, 1><<<g2, 256, SM2>>>(Hh, Hl, W2h, W2l, b2, HID, DIM,
                                           Yh, Yl, y, Yacc, nullptr, tspan, s);
        hmma_gemm<128, 0><<<g1, 256, SM1>>>(Yh, Yl, W1h, W1l, b1, DIM, HID,
                                            Hh, Hl, nullptr, nullptr, nullptr, tspan, s);
        hmma_gemm<64, 2><<<g2, 256, SM2>>>(Hh, Hl, W2h, W2l, b2, HID, DIM,
                                           Yh, Yl, y, Yacc, nullptr, tspan, s);
        hmma_gemm<128, 0><<<g1, 256, SM1>>>(Yh, Yl, W1h, W1l, b1, DIM, HID,
                                            Hh, Hl, nullptr, nullptr, nullptr, tspan, s);
        hmma_gemm<64, 3><<<g2, 256, SM2>>>(Hh, Hl, W2h, W2l, b2, HID, DIM,
                                           Yh, Yl, y, Yacc, nullptr, tspan, s);
        hmma_gemm<128, 0><<<g1, 256, SM1>>>(Yh, Yl, W1h, W1l, b1, DIM, HID,
                                            Hh, Hl, nullptr, nullptr, nullptr, tspan, s);
        hmma_gemm<64, 4><<<g2, 256, SM2>>>(Hh, Hl, W2h, W2l, b2, HID, DIM,
                                           Yh, Yl, nullptr, Yacc, ynext, tspan, s);
    }
}

// round 5
// speedup vs baseline: 3.6687x; 1.0188x over previous
#include <cuda_runtime.h>
#include <cuda_bf16.h>
#include <cstdint>
#include <cstddef>

#define BATCH 1024
#define DIM   1024
#define HID   4096
#define TSTEPS 16
#define BD (BATCH*DIM)

__device__ __nv_bfloat16 g_W1h[(size_t)HID * DIM];
__device__ __nv_bfloat16 g_W1l[(size_t)HID * DIM];
__device__ __nv_bfloat16 g_W2h[(size_t)DIM * HID];
__device__ __nv_bfloat16 g_W2l[(size_t)DIM * HID];
__device__ __nv_bfloat16 g_Hh[(size_t)BATCH * HID];
__device__ __nv_bfloat16 g_Hl[(size_t)BATCH * HID];
__device__ __nv_bfloat16 g_Yh[BD];
__device__ __nv_bfloat16 g_Yl[BD];
__device__ float         g_Yacc[BD];

__device__ __forceinline__ uint32_t smem_u32(const void* p) {
    uint32_t a;
    asm("{ .reg .u64 t; cvta.to.shared.u64 t, %1; cvt.u32.u64 %0, t; }" : "=r"(a) : "l"(p));
    return a;
}
__device__ __forceinline__ void cpa16(uint32_t s, const void* g) {
    asm volatile("cp.async.cg.shared.global [%0], [%1], 16;"
                 :: "r"(s), "l"(__cvta_generic_to_global(g)));
}
#define CP_COMMIT() asm volatile("cp.async.commit_group;" ::: "memory")
#define CP_WAIT0()  asm volatile("cp.async.wait_group 0;" ::: "memory")

__device__ __forceinline__ void ldsm4(uint32_t* r, uint32_t addr) {
    asm volatile("ldmatrix.sync.aligned.m8n8.x4.shared.b16 {%0,%1,%2,%3}, [%4];"
                 : "=r"(r[0]), "=r"(r[1]), "=r"(r[2]), "=r"(r[3]) : "r"(addr));
}
__device__ __forceinline__ void mma_bf16(float* d, const uint32_t* a, const uint32_t* b) {
    asm volatile(
        "mma.sync.aligned.m16n8k16.row.col.f32.bf16.bf16.f32 "
        "{%0,%1,%2,%3}, {%4,%5,%6,%7}, {%8,%9}, {%0,%1,%2,%3};"
        : "+f"(d[0]), "+f"(d[1]), "+f"(d[2]), "+f"(d[3])
        : "r"(a[0]), "r"(a[1]), "r"(a[2]), "r"(a[3]), "r"(b[0]), "r"(b[1]));
}

__device__ __forceinline__ uint32_t split_pack(float a0, float a1, uint32_t& lo) {
    __nv_bfloat16 h0 = __float2bfloat16(a0);
    __nv_bfloat16 h1 = __float2bfloat16(a1);
    __nv_bfloat16 l0 = __float2bfloat16(a0 - __bfloat162float(h0));
    __nv_bfloat16 l1 = __float2bfloat16(a1 - __bfloat162float(h1));
    lo = ((uint32_t)__bfloat16_as_ushort(l1) << 16) | __bfloat16_as_ushort(l0);
    return ((uint32_t)__bfloat16_as_ushort(h1) << 16) | __bfloat16_as_ushort(h0);
}

// C tile [BM x 64] of A[M,K] @ B[N,K]^T via mma.sync bf16, split hi/lo 3-term.
// 256 threads, 8 warps as 4(M) x 2(N). MI = BM/64 m16-frags per warp.
// 2 CTAs/SM (double-buffered BK=64 stages fit 2x in smem; regs capped 128).
// EPI 0: O = tanh(acc+bias) -> Oh/Ol
// EPI 1: k=acc+bias; o=Yin+h/2*k; Yacc=Yin+h/6*k;  o->Oh/Ol
// EPI 2: k=acc+bias; o=Yin+h/2*k; Yacc+=h/3*k;     o->Oh/Ol
// EPI 3: k=acc+bias; o=Yin+h*k;   Yacc+=h/3*k;     o->Oh/Ol
// EPI 4: k=acc+bias; o=Yacc+h/6*k; o->Yout(f32) and Oh/Ol
template <int BM, int EPI>
__global__ void __launch_bounds__(256, 2)
hmma_gemm(const __nv_bfloat16* __restrict__ Ah, const __nv_bfloat16* __restrict__ Al,
          const __nv_bfloat16* __restrict__ Bh, const __nv_bfloat16* __restrict__ Bl,
          const float* __restrict__ bias, int K, int ldc,
          __nv_bfloat16* __restrict__ Oh, __nv_bfloat16* __restrict__ Ol,
          const float* __restrict__ Yin, float* __restrict__ Yacc,
          float* __restrict__ Yout, const float* __restrict__ tspan, int step) {
    constexpr int BN = 64;
    constexpr int MI = BM / 64;          // m16 fragments per warp
    constexpr int NT = 4;                // n8 fragments per warp (warp covers 32 cols)
    constexpr int APLANE = BM * 128;     // bytes per plane: BM rows x 128B (BK=64 bf16)
    constexpr int BPLANE = BN * 128;
    constexpr int STAGE = 2 * APLANE + 2 * BPLANE;
    extern __shared__ char smem[];
    const uint32_t sb0 = smem_u32(smem);

    const int tid = threadIdx.x;
    const int wid = tid >> 5, lane = tid & 31;
    const int wm = wid & 3, wn = wid >> 2;
    const int gid = lane >> 2, tig = lane & 3;
    const int rowBase = blockIdx.y * BM;
    const int colBase = blockIdx.x * BN;
    const int NC = K >> 6;

    auto load_stage = [&](int kc, int st) {
        const uint32_t sb = sb0 + st * STAGE;
        const size_t keB = (size_t)kc * 128;  // byte offset along K
#pragma unroll
        for (int c = tid; c < BM * 8; c += 256) {
            const int row = c >> 3, kb = (c & 7) << 4;
            const uint32_t so = row * 128 + (kb ^ ((row & 7) << 4));
            const size_t g = (size_t)(rowBase + row) * (K * 2) + keB + kb;
            cpa16(sb + so, (const char*)Ah + g);
            cpa16(sb + APLANE + so, (const char*)Al + g);
        }
#pragma unroll
        for (int c = tid; c < BN * 8; c += 256) {
            const int row = c >> 3, kb = (c & 7) << 4;
            const uint32_t so = row * 128 + (kb ^ ((row & 7) << 4));
            const size_t g = (size_t)(colBase + row) * (K * 2) + keB + kb;
            cpa16(sb + 2 * APLANE + so, (const char*)Bh + g);
            cpa16(sb + 2 * APLANE + BPLANE + so, (const char*)Bl + g);
        }
    };

    float acc[MI][NT][4];
#pragma unroll
    for (int i = 0; i < MI; ++i)
#pragma unroll
        for (int j = 0; j < NT; ++j)
#pragma unroll
            for (int e = 0; e < 4; ++e) acc[i][j][e] = 0.f;

    load_stage(0, 0);
    CP_COMMIT();

    for (int kc = 0; kc < NC; ++kc) {
        CP_WAIT0();
        __syncthreads();
        if (kc + 1 < NC) { load_stage(kc + 1, (kc + 1) & 1); CP_COMMIT(); }
        const uint32_t sb = sb0 + (kc & 1) * STAGE;
#pragma unroll
        for (int t = 0; t < 4; ++t) {  // four k16 slices per BK=64 chunk
            uint32_t af[2][MI][4];     // [plane hi/lo][mi][4 regs]
#pragma unroll
            for (int mi = 0; mi < MI; ++mi) {
                const int arow = wm * (16 * MI) + mi * 16 + (lane & 15);
                const int kb = t * 32 + ((lane >> 4) << 4);
                const uint32_t so = arow * 128 + (kb ^ ((arow & 7) << 4));
                ldsm4(af[0][mi], sb + so);
                ldsm4(af[1][mi], sb + APLANE + so);
            }
            uint32_t bfh[NT * 2], bfl[NT * 2];
#pragma unroll
            for (int bi = 0; bi < NT / 2; ++bi) {
                const int brow = wn * 32 + bi * 16 + ((lane >> 4) << 3) + (lane & 7);
                const int kb = t * 32 + (((lane >> 3) & 1) << 4);
                const uint32_t so = brow * 128 + (kb ^ ((brow & 7) << 4));
                ldsm4(&bfh[bi * 4], sb + 2 * APLANE + so);
                ldsm4(&bfl[bi * 4], sb + 2 * APLANE + BPLANE + so);
            }
#pragma unroll
            for (int mi = 0; mi < MI; ++mi)
#pragma unroll
                for (int ni = 0; ni < NT; ++ni) {
                    mma_bf16(acc[mi][ni], af[0][mi], &bfh[ni * 2]);
                    mma_bf16(acc[mi][ni], af[0][mi], &bfl[ni * 2]);
                    mma_bf16(acc[mi][ni], af[1][mi], &bfh[ni * 2]);
                }
        }
    }

    float h = 0.f;
    if (EPI >= 1) h = tspan[step + 1] - tspan[step];

    auto emit = [&](int row, int col, float v0, float v1) {
        const float2 bb = *reinterpret_cast<const float2*>(bias + col);
        v0 += bb.x;
        v1 += bb.y;
        const size_t ix = (size_t)row * ldc + col;
        float o0, o1;
        if (EPI == 0) {
            o0 = tanhf(v0);
            o1 = tanhf(v1);
        } else if (EPI == 1) {
            const float2 yy = *reinterpret_cast<const float2*>(Yin + ix);
            o0 = fmaf(0.5f * h, v0, yy.x);
            o1 = fmaf(0.5f * h, v1, yy.y);
            float2 aa;
            aa.x = fmaf(h * (1.f / 6.f), v0, yy.x);
            aa.y = fmaf(h * (1.f / 6.f), v1, yy.y);
            *reinterpret_cast<float2*>(Yacc + ix) = aa;
        } else if (EPI == 2 || EPI == 3) {
            const float cy = (EPI == 2) ? 0.5f : 1.0f;
            const float2 yy = *reinterpret_cast<const float2*>(Yin + ix);
            float2 aa = *reinterpret_cast<float2*>(Yacc + ix);
            o0 = fmaf(cy * h, v0, yy.x);
            o1 = fmaf(cy * h, v1, yy.y);
            aa.x = fmaf(h * (1.f / 3.f), v0, aa.x);
            aa.y = fmaf(h * (1.f / 3.f), v1, aa.y);
            *reinterpret_cast<float2*>(Yacc + ix) = aa;
        } else {
            const float2 aa = *reinterpret_cast<const float2*>(Yacc + ix);
            o0 = fmaf(h * (1.f / 6.f), v0, aa.x);
            o1 = fmaf(h * (1.f / 6.f), v1, aa.y);
            float2 oo;
            oo.x = o0;
            oo.y = o1;
            *reinterpret_cast<float2*>(Yout + ix) = oo;
        }
        uint32_t lo;
        const uint32_t hi = split_pack(o0, o1, lo);
        *reinterpret_cast<uint32_t*>(Oh + ix) = hi;
        *reinterpret_cast<uint32_t*>(Ol + ix) = lo;
    };

#pragma unroll
    for (int mi = 0; mi < MI; ++mi) {
        const int row = rowBase + wm * (16 * MI) + mi * 16 + gid;
#pragma unroll
        for (int ni = 0; ni < NT; ++ni) {
            const int col = colBase + wn * 32 + ni * 8 + tig * 2;
            emit(row, col, acc[mi][ni][0], acc[mi][ni][1]);
            emit(row + 8, col, acc[mi][ni][2], acc[mi][ni][3]);
        }
    }
}

__global__ void ktrans_split(const float* __restrict__ in,
                             __nv_bfloat16* __restrict__ oh,
                             __nv_bfloat16* __restrict__ ol, int R, int C) {
    __shared__ float t[32][33];
    const int bx = blockIdx.x * 32;
    const int by = blockIdx.y * 32;
    for (int i = threadIdx.y; i < 32; i += 8)
        t[i][threadIdx.x] = in[(size_t)(by + i) * C + bx + threadIdx.x];
    __syncthreads();
    for (int i = threadIdx.y; i < 32; i += 8) {
        float v = t[threadIdx.x][i];
        size_t o = (size_t)(bx + i) * R + by + threadIdx.x;
        __nv_bfloat16 hb = __float2bfloat16(v);
        oh[o] = hb;
        ol[o] = __float2bfloat16(v - __bfloat162float(hb));
    }
}

__global__ void ksplit(const float* __restrict__ in, __nv_bfloat16* __restrict__ oh,
                       __nv_bfloat16* __restrict__ ol, int n) {
    int i = blockIdx.x * 256 + threadIdx.x;
    if (i < n) {
        float v = in[i];
        __nv_bfloat16 hb = __float2bfloat16(v);
        oh[i] = hb;
        ol[i] = __float2bfloat16(v - __bfloat162float(hb));
    }
}

extern "C" void kernel_launch(void* const* d_in, const int* in_sizes, int n_in,
                              void* d_out, int out_size) {
    const float* y_init = (const float*)d_in[0];
    const float* tspan = (const float*)d_in[1];
    const float* W1 = (const float*)d_in[2];
    const float* b1 = (const float*)d_in[3];
    const float* W2 = (const float*)d_in[4];
    const float* b2 = (const float*)d_in[5];
    float* out = (float*)d_out;

    __nv_bfloat16 *W1h, *W1l, *W2h, *W2l, *Hh, *Hl, *Yh, *Yl;
    float* Yacc;
    cudaGetSymbolAddress((void**)&W1h, g_W1h);
    cudaGetSymbolAddress((void**)&W1l, g_W1l);
    cudaGetSymbolAddress((void**)&W2h, g_W2h);
    cudaGetSymbolAddress((void**)&W2l, g_W2l);
    cudaGetSymbolAddress((void**)&Hh, g_Hh);
    cudaGetSymbolAddress((void**)&Hl, g_Hl);
    cudaGetSymbolAddress((void**)&Yh, g_Yh);
    cudaGetSymbolAddress((void**)&Yl, g_Yl);
    cudaGetSymbolAddress((void**)&Yacc, g_Yacc);

    // dynamic smem: 2 stages x (2 A planes + 2 B planes); 2 CTAs per SM
    const int SM1 = 2 * (2 * 128 * 128 + 2 * 64 * 128);  // 98304 (BM=128)
    const int SM2 = 2 * (2 * 64 * 128 + 2 * 64 * 128);   // 65536 (BM=64)
    cudaFuncSetAttribute(hmma_gemm<128, 0>, cudaFuncAttributeMaxDynamicSharedMemorySize, SM1);
    cudaFuncSetAttribute(hmma_gemm<64, 1>, cudaFuncAttributeMaxDynamicSharedMemorySize, SM2);
    cudaFuncSetAttribute(hmma_gemm<64, 2>, cudaFuncAttributeMaxDynamicSharedMemorySize, SM2);
    cudaFuncSetAttribute(hmma_gemm<64, 3>, cudaFuncAttributeMaxDynamicSharedMemorySize, SM2);
    cudaFuncSetAttribute(hmma_gemm<64, 4>, cudaFuncAttributeMaxDynamicSharedMemorySize, SM2);

    // out = [ t_span (16) | traj (16 x 1024 x 1024) ], traj[0] = y_init
    cudaMemcpyAsync(out, tspan, TSTEPS * sizeof(float), cudaMemcpyDeviceToDevice, 0);
    float* traj = out + TSTEPS;
    cudaMemcpyAsync(traj, y_init, (size_t)BD * sizeof(float), cudaMemcpyDeviceToDevice, 0);

    ktrans_split<<<dim3(HID / 32, DIM / 32), dim3(32, 8)>>>(W1, W1h, W1l, DIM, HID);
    ktrans_split<<<dim3(DIM / 32, HID / 32), dim3(32, 8)>>>(W2, W2h, W2l, HID, DIM);
    ksplit<<<BD / 256, 256>>>(y_init, Yh, Yl, BD);

    const dim3 g1(HID / 64, BATCH / 128);  // (64, 8)  = 512 CTAs, BM=128
    const dim3 g2(DIM / 64, BATCH / 64);   // (16, 16) = 256 CTAs, BM=64

    for (int s = 0; s < TSTEPS - 1; ++s) {
        const float* y = traj + (size_t)s * BD;
        float* ynext = traj + (size_t)(s + 1) * BD;

        hmma_gemm<128, 0><<<g1, 256, SM1>>>(Yh, Yl, W1h, W1l, b1, DIM, HID,
                                            Hh, Hl, nullptr, nullptr, nullptr, tspan, s);
        hmma_gemm<64, 1><<<g2, 256, SM2>>>(Hh, Hl, W2h, W2l, b2, HID, DIM,
                                           Yh, Yl, y, Yacc, nullptr, tspan, s);
        hmma_gemm<128, 0><<<g1, 256, SM1>>>(Yh, Yl, W1h, W1l, b1, DIM, HID,
                                            Hh, Hl, nullptr, nullptr, nullptr, tspan, s);
        hmma_gemm<64, 2><<<g2, 256, SM2>>>(Hh, Hl, W2h, W2l, b2, HID, DIM,
                                           Yh, Yl, y, Yacc, nullptr, tspan, s);
        hmma_gemm<128, 0><<<g1, 256, SM1>>>(Yh, Yl, W1h, W1l, b1, DIM, HID,
                                            Hh, Hl, nullptr, nullptr, nullptr, tspan, s);
        hmma_gemm<64, 3><<<g2, 256, SM2>>>(Hh, Hl, W2h, W2l, b2, HID, DIM,
                                           Yh, Yl, y, Yacc, nullptr, tspan, s);
        hmma_gemm<128, 0><<<g1, 256, SM1>>>(Yh, Yl, W1h, W1l, b1, DIM, HID,
                                            Hh, Hl, nullptr, nullptr, nullptr, tspan, s);
        hmma_gemm<64, 4><<<g2, 256, SM2>>>(Hh, Hl, W2h, W2l, b2, HID, DIM,
                                           Yh, Yl, nullptr, Yacc, ynext, tspan, s);
    }
}